// round 7
// baseline (speedup 1.0000x reference)
#include <cuda_runtime.h>
#include <math.h>

#define NN 50000
#define EE 600000
#define DD 128
#define HH 4
#define CC 32
#define ETOT (EE + NN)
#define NEG 0.2f

#define PREP_EPT 4
#define PREP_BLOCKS ((ETOT + 256 * PREP_EPT - 1) / (256 * PREP_EPT))
#define FILL_EPT 4
#define FILL_BLOCKS ((ETOT + 256 * FILL_EPT - 1) / (256 * FILL_EPT))

// ---------------- scratch (device globals; no allocation allowed) ----------
__device__ __align__(16) float g_h[NN * DD];       // transformed feats
__device__ __align__(16) float g_asrc[NN * HH];    // per-node src logits
__device__ __align__(16) float g_adst[NN * HH];    // per-node dst logits
__device__ int g_cnt[NN];                           // degree histogram
__device__ int g_row[NN + 1];                       // CSR row offsets (by dst)
__device__ int g_csr[ETOT];                         // src per CSR slot
__device__ int g_pos[ETOT];                         // within-row slot per edge
__device__ int g_srcv[ETOT];                        // int32 src per edge
__device__ int g_dstv[ETOT];                        // int32 dst per edge
__device__ int g_is64;                              // edge dtype flag

__device__ __forceinline__ float lrelu(float x) { return x > 0.f ? x : NEG * x; }

__device__ __forceinline__ long long ld_idx(const void* ei, int pos) {
    if (g_is64) return ((const long long*)ei)[pos];
    return (long long)((const int*)ei)[pos];
}

// f32x2 packed-FMA helpers (FFMA2 is only reachable via PTX on sm_103a)
__device__ __forceinline__ unsigned long long pk2(float a, float b) {
    unsigned long long r;
    asm("mov.b64 %0,{%1,%2};" : "=l"(r) : "f"(a), "f"(b));
    return r;
}
__device__ __forceinline__ void upk2(unsigned long long v, float& a, float& b) {
    asm("mov.b64 {%0,%1},%2;" : "=f"(a), "=f"(b) : "l"(v));
}
__device__ __forceinline__ void fma2(unsigned long long& d,
                                     unsigned long long a, unsigned long long b) {
    asm("fma.rn.f32x2 %0,%1,%2,%0;" : "+l"(d) : "l"(a), "l"(b));
}

// ---------------- K0: zero g_cnt + parallel dtype detect -------------------
__global__ void k_init(const int* ei) {
    int i = blockIdx.x * blockDim.x + threadIdx.x;
    if (i < NN) g_cnt[i] = 0;
    if (blockIdx.x == 0 && threadIdx.x < 32) {
        // int64 indices < 2^31: every odd 32-bit word is 0. One word per lane.
        int v = ei[2 * threadIdx.x + 1];
        unsigned nz = __ballot_sync(0xFFFFFFFFu, v != 0);
        if (threadIdx.x == 0) g_is64 = (nz == 0u);
    }
}

// ---------------- K1: h = x @ W (f32x2) + fused attention logits -----------
__global__ void k_gemm(const float* __restrict__ x, const float* __restrict__ W,
                       const float* __restrict__ att_src,
                       const float* __restrict__ att_dst) {
    extern __shared__ float sm[];
    float* Wsh = sm;             // 128*128
    float* Xsh = sm + DD * DD;   // 32*128
    const int tx = threadIdx.x;
    const int node0 = blockIdx.x * 32;

    for (int idx = tx; idx < (DD * DD) / 4; idx += blockDim.x)
        ((float4*)Wsh)[idx] = ((const float4*)W)[idx];

    for (int idx = tx; idx < (32 * DD) / 4; idx += blockDim.x) {
        int r = idx / (DD / 4);
        int c = idx % (DD / 4);
        int row = node0 + r;
        float4 v = make_float4(0.f, 0.f, 0.f, 0.f);
        if (row < NN) v = ((const float4*)(x + (size_t)row * DD))[c];
        ((float4*)(Xsh + r * DD))[c] = v;
    }
    __syncthreads();

    const int c4 = tx & 31;        // 4-col group (cols c4*4 .. c4*4+3)
    const int rb = (tx >> 5) * 4;  // 4-row base within tile
    const float4* Wsh4 = (const float4*)Wsh;
    const float4* Xsh4 = (const float4*)Xsh;

    unsigned long long a01[4], a23[4];
    #pragma unroll
    for (int j = 0; j < 4; j++) { a01[j] = 0ull; a23[j] = 0ull; }

    for (int k4 = 0; k4 < DD / 4; k4++) {
        float xv[4][4];
        #pragma unroll
        for (int j = 0; j < 4; j++) {
            float4 t = Xsh4[(rb + j) * 32 + k4];
            xv[j][0] = t.x; xv[j][1] = t.y; xv[j][2] = t.z; xv[j][3] = t.w;
        }
        #pragma unroll
        for (int kk = 0; kk < 4; kk++) {
            float4 w = Wsh4[(4 * k4 + kk) * 32 + c4];
            unsigned long long wl = pk2(w.x, w.y);
            unsigned long long wh = pk2(w.z, w.w);
            #pragma unroll
            for (int j = 0; j < 4; j++) {
                unsigned long long xx = pk2(xv[j][kk], xv[j][kk]);
                fma2(a01[j], xx, wl);
                fma2(a23[j], xx, wh);
            }
        }
    }

    float accf[4][4];
    #pragma unroll
    for (int j = 0; j < 4; j++) {
        upk2(a01[j], accf[j][0], accf[j][1]);
        upk2(a23[j], accf[j][2], accf[j][3]);
    }

    #pragma unroll
    for (int j = 0; j < 4; j++) {
        int row = node0 + rb + j;
        if (row < NN) {
            float4 o = make_float4(accf[j][0], accf[j][1], accf[j][2], accf[j][3]);
            ((float4*)(g_h + (size_t)row * DD))[c4] = o;
        }
    }

    float4 as4 = ((const float4*)att_src)[c4];
    float4 ad4 = ((const float4*)att_dst)[c4];
    const int head = c4 >> 3;
    #pragma unroll
    for (int j = 0; j < 4; j++) {
        float ps = accf[j][0] * as4.x + accf[j][1] * as4.y +
                   accf[j][2] * as4.z + accf[j][3] * as4.w;
        float pd = accf[j][0] * ad4.x + accf[j][1] * ad4.y +
                   accf[j][2] * ad4.z + accf[j][3] * ad4.w;
        #pragma unroll
        for (int o = 4; o; o >>= 1) {
            ps += __shfl_xor_sync(0xFFFFFFFFu, ps, o);
            pd += __shfl_xor_sync(0xFFFFFFFFu, pd, o);
        }
        int row = node0 + rb + j;
        if ((c4 & 7) == 0 && row < NN) {
            g_asrc[row * HH + head] = ps;
            g_adst[row * HH + head] = pd;
        }
    }
}

// ---------------- K2: edge prep — int32 convert + degree hist + slot -------
__global__ void k_prep(const void* __restrict__ ei) {
    int base = blockIdx.x * 256 * PREP_EPT;
    int s[PREP_EPT], d[PREP_EPT], e[PREP_EPT];
    #pragma unroll
    for (int k = 0; k < PREP_EPT; k++) {
        e[k] = base + k * 256 + threadIdx.x;
        if (e[k] < ETOT) {
            if (e[k] < EE) {
                s[k] = (int)ld_idx(ei, e[k]);
                d[k] = (int)ld_idx(ei, EE + e[k]);
            } else {
                s[k] = d[k] = e[k] - EE;
            }
        }
    }
    #pragma unroll
    for (int k = 0; k < PREP_EPT; k++) {
        if (e[k] < ETOT) {
            g_srcv[e[k]] = s[k];
            g_dstv[e[k]] = d[k];
            g_pos[e[k]] = atomicAdd(&g_cnt[d[k]], 1);
        }
    }
}

// ---------------- K3: single-block exclusive scan g_cnt -> g_row -----------
__global__ void k_scan() {
    __shared__ int wsum[32];
    const int T = 1024;
    const int tid = threadIdx.x;
    const int CH = (NN + T - 1) / T;   // 49
    int lo = tid * CH;
    int hi = lo + CH; if (hi > NN) hi = NN;
    int s = 0;
    for (int i = lo; i < hi; i++) s += g_cnt[i];

    int lane = tid & 31, w = tid >> 5;
    int xv = s;
    #pragma unroll
    for (int o = 1; o < 32; o <<= 1) {
        int t = __shfl_up_sync(0xFFFFFFFFu, xv, o);
        if (lane >= o) xv += t;
    }
    if (lane == 31) wsum[w] = xv;
    __syncthreads();
    if (w == 0) {
        int v = wsum[lane];
        #pragma unroll
        for (int o = 1; o < 32; o <<= 1) {
            int t = __shfl_up_sync(0xFFFFFFFFu, v, o);
            if (lane >= o) v += t;
        }
        wsum[lane] = v;
    }
    __syncthreads();
    int run = (xv - s) + (w > 0 ? wsum[w - 1] : 0);   // exclusive prefix
    for (int i = lo; i < hi; i++) {
        g_row[i] = run;
        run += g_cnt[i];
    }
    if (tid == T - 1) g_row[NN] = ETOT;
}

// ---------------- K4: fill CSR (no atomics — slot precomputed) -------------
__global__ void k_fill() {
    int base = blockIdx.x * 256 * FILL_EPT;
    #pragma unroll
    for (int k = 0; k < FILL_EPT; k++) {
        int e = base + k * 256 + threadIdx.x;
        if (e < ETOT)
            g_csr[g_row[g_dstv[e]] + g_pos[e]] = g_srcv[e];
    }
}

// ---------------- K5: fused softmax + aggregation + GELU/LN/residual -------
__global__ void k_node(const float* __restrict__ x,
                       const float* __restrict__ bias,
                       const float* __restrict__ gamma,
                       const float* __restrict__ beta,
                       float* __restrict__ out) {
    int gid = blockIdx.x * blockDim.x + threadIdx.x;
    int n = gid >> 5;
    if (n >= NN) return;
    int l = gid & 31;
    int head = l >> 3;
    int beg = g_row[n], end = g_row[n + 1];
    float adh = g_adst[(size_t)n * HH + head];

    float4 acc = make_float4(0.f, 0.f, 0.f, 0.f);
    float dacc = 0.f;
    int idx = beg;
    for (; idx + 1 < end; idx += 2) {
        int s0 = __ldg(g_csr + idx);
        int s1 = __ldg(g_csr + idx + 1);
        float a0 = __ldg(g_asrc + (size_t)s0 * HH + head);
        float a1 = __ldg(g_asrc + (size_t)s1 * HH + head);
        float4 h0 = ((const float4*)(g_h + (size_t)s0 * DD))[l];
        float4 h1 = ((const float4*)(g_h + (size_t)s1 * DD))[l];
        float w0 = __expf(lrelu(a0 + adh));
        float w1 = __expf(lrelu(a1 + adh));
        acc.x = fmaf(w0, h0.x, acc.x); acc.y = fmaf(w0, h0.y, acc.y);
        acc.z = fmaf(w0, h0.z, acc.z); acc.w = fmaf(w0, h0.w, acc.w);
        acc.x = fmaf(w1, h1.x, acc.x); acc.y = fmaf(w1, h1.y, acc.y);
        acc.z = fmaf(w1, h1.z, acc.z); acc.w = fmaf(w1, h1.w, acc.w);
        dacc += w0 + w1;
    }
    if (idx < end) {
        int s0 = __ldg(g_csr + idx);
        float a0 = __ldg(g_asrc + (size_t)s0 * HH + head);
        float4 h0 = ((const float4*)(g_h + (size_t)s0 * DD))[l];
        float w0 = __expf(lrelu(a0 + adh));
        acc.x = fmaf(w0, h0.x, acc.x); acc.y = fmaf(w0, h0.y, acc.y);
        acc.z = fmaf(w0, h0.z, acc.z); acc.w = fmaf(w0, h0.w, acc.w);
        dacc += w0;
    }
    float inv = 1.f / dacc;   // denom >= exp(self) > 0 always

    float4 b = ((const float4*)bias)[l];
    float v0 = acc.x * inv + b.x;
    float v1 = acc.y * inv + b.y;
    float v2 = acc.z * inv + b.z;
    float v3 = acc.w * inv + b.w;
    const float kc = 0.70710678118654752f;
    float g0 = 0.5f * v0 * (1.f + erff(v0 * kc));
    float g1 = 0.5f * v1 * (1.f + erff(v1 * kc));
    float g2 = 0.5f * v2 * (1.f + erff(v2 * kc));
    float g3 = 0.5f * v3 * (1.f + erff(v3 * kc));
    float s1 = g0 + g1 + g2 + g3;
    float s2 = g0 * g0 + g1 * g1 + g2 * g2 + g3 * g3;
    #pragma unroll
    for (int o = 16; o; o >>= 1) {
        s1 += __shfl_xor_sync(0xFFFFFFFFu, s1, o);
        s2 += __shfl_xor_sync(0xFFFFFFFFu, s2, o);
    }
    float mean = s1 * (1.f / DD);
    float var  = s2 * (1.f / DD) - mean * mean;
    float invs = rsqrtf(var + 1e-5f);
    float4 ga = ((const float4*)gamma)[l];
    float4 be = ((const float4*)beta)[l];
    float4 xr = ((const float4*)(x + (size_t)n * DD))[l];
    float4 o4;
    o4.x = (g0 - mean) * invs * ga.x + be.x + xr.x;
    o4.y = (g1 - mean) * invs * ga.y + be.y + xr.y;
    o4.z = (g2 - mean) * invs * ga.z + be.z + xr.z;
    o4.w = (g3 - mean) * invs * ga.w + be.w + xr.w;
    ((float4*)(out + (size_t)n * DD))[l] = o4;
}

// ---------------- host -----------------------------------------------------
extern "C" void kernel_launch(void* const* d_in, const int* in_sizes, int n_in,
                              void* d_out, int out_size) {
    const float* x       = (const float*)d_in[0];
    const void*  ei      = d_in[1];  // int32 or int64; sniffed on device
    const float* W       = (const float*)d_in[2];
    const float* att_src = (const float*)d_in[3];
    const float* att_dst = (const float*)d_in[4];
    const float* bias    = (const float*)d_in[5];
    const float* gamma   = (const float*)d_in[6];
    const float* beta    = (const float*)d_in[7];
    float* out = (float*)d_out;

    const int SMEM = (DD * DD + 32 * DD) * (int)sizeof(float);  // 80KB
    cudaFuncSetAttribute(k_gemm, cudaFuncAttributeMaxDynamicSharedMemorySize, SMEM);

    k_init<<<(NN + 255) / 256, 256>>>((const int*)ei);
    k_prep<<<PREP_BLOCKS, 256>>>(ei);
    k_gemm<<<(NN + 31) / 32, 256, SMEM>>>(x, W, att_src, att_dst);
    k_scan<<<1, 1024>>>();
    k_fill<<<FILL_BLOCKS, 256>>>();
    {
        long long total = (long long)NN * 32;
        int blocks = (int)((total + 255) / 256);
        k_node<<<blocks, 256>>>(x, bias, gamma, beta, out);
    }
}

// round 9
// speedup vs baseline: 2.0629x; 2.0629x over previous
#include <cuda_runtime.h>
#include <math.h>

#define NN 50000
#define EE 600000
#define DD 128
#define HH 4
#define CC 32
#define ETOT (EE + NN)
#define NEG 0.2f
#define NBLK_SCAN ((NN + 255) / 256)   // 196

#define PREP_EPT 4
#define PREP_BLOCKS ((ETOT + 256 * PREP_EPT - 1) / (256 * PREP_EPT))
#define FILL_EPT 4
#define FILL_BLOCKS ((ETOT + 256 * FILL_EPT - 1) / (256 * FILL_EPT))

// ---------------- scratch (device globals; no allocation allowed) ----------
__device__ __align__(16) float g_h[NN * DD];       // transformed feats
__device__ __align__(16) float g_asrc[NN * HH];    // per-node src logits
__device__ __align__(16) float g_adst[NN * HH];    // per-node dst logits
__device__ int g_cnt[NN];                           // degree histogram
__device__ int g_rowtmp[NN];                        // per-chunk exclusive scan
__device__ int g_bsum[NBLK_SCAN];                   // chunk sums
__device__ int g_row[NN + 1];                       // CSR row offsets (by dst)
__device__ int g_csr[ETOT];                         // src per CSR slot
__device__ int g_pos[ETOT];                         // within-row slot per edge
__device__ int g_srcv[ETOT];                        // int32 src per edge
__device__ int g_dstv[ETOT];                        // int32 dst per edge
__device__ int g_is64;                              // edge dtype flag

__device__ __forceinline__ float lrelu(float x) { return x > 0.f ? x : NEG * x; }

__device__ __forceinline__ long long ld_idx(const void* ei, int pos) {
    if (g_is64) return ((const long long*)ei)[pos];
    return (long long)((const int*)ei)[pos];
}

// f32x2 packed-FMA helpers (FFMA2 is only reachable via PTX on sm_103a)
__device__ __forceinline__ unsigned long long pk2(float a, float b) {
    unsigned long long r;
    asm("mov.b64 %0,{%1,%2};" : "=l"(r) : "f"(a), "f"(b));
    return r;
}
__device__ __forceinline__ void upk2(unsigned long long v, float& a, float& b) {
    asm("mov.b64 {%0,%1},%2;" : "=f"(a), "=f"(b) : "l"(v));
}
__device__ __forceinline__ void fma2(unsigned long long& d,
                                     unsigned long long a, unsigned long long b) {
    asm("fma.rn.f32x2 %0,%1,%2,%0;" : "+l"(d) : "l"(a), "l"(b));
}

// ---------------- K0: zero g_cnt + parallel dtype detect -------------------
__global__ void k_init(const int* ei) {
    int i = blockIdx.x * blockDim.x + threadIdx.x;
    if (i < NN) g_cnt[i] = 0;
    if (blockIdx.x == 0 && threadIdx.x < 32) {
        // int64 indices < 2^31: every odd 32-bit word is 0. One word per lane.
        int v = ei[2 * threadIdx.x + 1];
        unsigned nz = __ballot_sync(0xFFFFFFFFu, v != 0);
        if (threadIdx.x == 0) g_is64 = (nz == 0u);
    }
}

// ---------------- K1: h = x @ W (f32x2) + fused attention logits -----------
__global__ void k_gemm(const float* __restrict__ x, const float* __restrict__ W,
                       const float* __restrict__ att_src,
                       const float* __restrict__ att_dst) {
    extern __shared__ float sm[];
    float* Wsh = sm;             // 128*128
    float* Xsh = sm + DD * DD;   // 32*128
    const int tx = threadIdx.x;
    const int node0 = blockIdx.x * 32;

    for (int idx = tx; idx < (DD * DD) / 4; idx += blockDim.x)
        ((float4*)Wsh)[idx] = ((const float4*)W)[idx];

    for (int idx = tx; idx < (32 * DD) / 4; idx += blockDim.x) {
        int r = idx / (DD / 4);
        int c = idx % (DD / 4);
        int row = node0 + r;
        float4 v = make_float4(0.f, 0.f, 0.f, 0.f);
        if (row < NN) v = ((const float4*)(x + (size_t)row * DD))[c];
        ((float4*)(Xsh + r * DD))[c] = v;
    }
    __syncthreads();

    const int c4 = tx & 31;        // 4-col group (cols c4*4 .. c4*4+3)
    const int rb = (tx >> 5) * 4;  // 4-row base within tile
    const float4* Wsh4 = (const float4*)Wsh;
    const float4* Xsh4 = (const float4*)Xsh;

    unsigned long long a01[4], a23[4];
    #pragma unroll
    for (int j = 0; j < 4; j++) { a01[j] = 0ull; a23[j] = 0ull; }

    for (int k4 = 0; k4 < DD / 4; k4++) {
        float xv[4][4];
        #pragma unroll
        for (int j = 0; j < 4; j++) {
            float4 t = Xsh4[(rb + j) * 32 + k4];
            xv[j][0] = t.x; xv[j][1] = t.y; xv[j][2] = t.z; xv[j][3] = t.w;
        }
        #pragma unroll
        for (int kk = 0; kk < 4; kk++) {
            float4 w = Wsh4[(4 * k4 + kk) * 32 + c4];
            unsigned long long wl = pk2(w.x, w.y);
            unsigned long long wh = pk2(w.z, w.w);
            #pragma unroll
            for (int j = 0; j < 4; j++) {
                unsigned long long xx = pk2(xv[j][kk], xv[j][kk]);
                fma2(a01[j], xx, wl);
                fma2(a23[j], xx, wh);
            }
        }
    }

    float accf[4][4];
    #pragma unroll
    for (int j = 0; j < 4; j++) {
        upk2(a01[j], accf[j][0], accf[j][1]);
        upk2(a23[j], accf[j][2], accf[j][3]);
    }

    #pragma unroll
    for (int j = 0; j < 4; j++) {
        int row = node0 + rb + j;
        if (row < NN) {
            float4 o = make_float4(accf[j][0], accf[j][1], accf[j][2], accf[j][3]);
            ((float4*)(g_h + (size_t)row * DD))[c4] = o;
        }
    }

    float4 as4 = ((const float4*)att_src)[c4];
    float4 ad4 = ((const float4*)att_dst)[c4];
    const int head = c4 >> 3;
    #pragma unroll
    for (int j = 0; j < 4; j++) {
        float ps = accf[j][0] * as4.x + accf[j][1] * as4.y +
                   accf[j][2] * as4.z + accf[j][3] * as4.w;
        float pd = accf[j][0] * ad4.x + accf[j][1] * ad4.y +
                   accf[j][2] * ad4.z + accf[j][3] * ad4.w;
        #pragma unroll
        for (int o = 4; o; o >>= 1) {
            ps += __shfl_xor_sync(0xFFFFFFFFu, ps, o);
            pd += __shfl_xor_sync(0xFFFFFFFFu, pd, o);
        }
        int row = node0 + rb + j;
        if ((c4 & 7) == 0 && row < NN) {
            g_asrc[row * HH + head] = ps;
            g_adst[row * HH + head] = pd;
        }
    }
}

// ---------------- K2: edge prep — int32 convert + degree hist + slot -------
__global__ void k_prep(const void* __restrict__ ei) {
    int base = blockIdx.x * 256 * PREP_EPT;
    int s[PREP_EPT], d[PREP_EPT], e[PREP_EPT];
    #pragma unroll
    for (int k = 0; k < PREP_EPT; k++) {
        e[k] = base + k * 256 + threadIdx.x;
        if (e[k] < ETOT) {
            if (e[k] < EE) {
                s[k] = (int)ld_idx(ei, e[k]);
                d[k] = (int)ld_idx(ei, EE + e[k]);
            } else {
                s[k] = d[k] = e[k] - EE;
            }
        }
    }
    #pragma unroll
    for (int k = 0; k < PREP_EPT; k++) {
        if (e[k] < ETOT) {
            g_srcv[e[k]] = s[k];
            g_dstv[e[k]] = d[k];
            g_pos[e[k]] = atomicAdd(&g_cnt[d[k]], 1);
        }
    }
}

// ---------------- K3a/b/c: multi-block exclusive scan g_cnt -> g_row -------
__global__ void k_scanA() {
    __shared__ int wsum[8];
    int i = blockIdx.x * 256 + threadIdx.x;
    int lane = threadIdx.x & 31, w = threadIdx.x >> 5;
    int v = (i < NN) ? g_cnt[i] : 0;
    int xv = v;
    #pragma unroll
    for (int o = 1; o < 32; o <<= 1) {
        int t = __shfl_up_sync(0xFFFFFFFFu, xv, o);
        if (lane >= o) xv += t;
    }
    if (lane == 31) wsum[w] = xv;
    __syncthreads();
    if (w == 0) {
        int s = (lane < 8) ? wsum[lane] : 0;
        #pragma unroll
        for (int o = 1; o < 8; o <<= 1) {
            int t = __shfl_up_sync(0xFFFFFFFFu, s, o);
            if (lane >= o) s += t;
        }
        if (lane < 8) wsum[lane] = s;
    }
    __syncthreads();
    int incl = xv + (w > 0 ? wsum[w - 1] : 0);
    if (i < NN) g_rowtmp[i] = incl - v;
    if (threadIdx.x == 255) g_bsum[blockIdx.x] = incl;
}

__global__ void k_scanB() {
    __shared__ int wsum[8];
    int i = threadIdx.x;
    int lane = i & 31, w = i >> 5;
    int v = (i < NBLK_SCAN) ? g_bsum[i] : 0;
    int xv = v;
    #pragma unroll
    for (int o = 1; o < 32; o <<= 1) {
        int t = __shfl_up_sync(0xFFFFFFFFu, xv, o);
        if (lane >= o) xv += t;
    }
    if (lane == 31) wsum[w] = xv;
    __syncthreads();
    if (w == 0) {
        int s = (lane < 8) ? wsum[lane] : 0;
        #pragma unroll
        for (int o = 1; o < 8; o <<= 1) {
            int t = __shfl_up_sync(0xFFFFFFFFu, s, o);
            if (lane >= o) s += t;
        }
        if (lane < 8) wsum[lane] = s;
    }
    __syncthreads();
    int incl = xv + (w > 0 ? wsum[w - 1] : 0);
    if (i < NBLK_SCAN) g_bsum[i] = incl - v;  // exclusive
}

__global__ void k_scanC() {
    int i = blockIdx.x * 256 + threadIdx.x;
    if (i < NN) g_row[i] = g_rowtmp[i] + g_bsum[blockIdx.x];
    if (i == 0) g_row[NN] = ETOT;
}

// ---------------- K4: fill CSR (no atomics — slot precomputed) -------------
__global__ void k_fill() {
    int base = blockIdx.x * 256 * FILL_EPT;
    #pragma unroll
    for (int k = 0; k < FILL_EPT; k++) {
        int e = base + k * 256 + threadIdx.x;
        if (e < ETOT)
            g_csr[g_row[g_dstv[e]] + g_pos[e]] = g_srcv[e];
    }
}

// ---------------- K5: fused softmax + aggregation + GELU/LN/residual -------
__global__ void k_node(const float* __restrict__ x,
                       const float* __restrict__ bias,
                       const float* __restrict__ gamma,
                       const float* __restrict__ beta,
                       float* __restrict__ out) {
    int gid = blockIdx.x * blockDim.x + threadIdx.x;
    int n = gid >> 5;
    if (n >= NN) return;
    int l = gid & 31;
    int head = l >> 3;
    int beg = g_row[n], end = g_row[n + 1];
    float adh = g_adst[(size_t)n * HH + head];

    float4 acc = make_float4(0.f, 0.f, 0.f, 0.f);
    float dacc = 0.f;
    int idx = beg;
    for (; idx + 1 < end; idx += 2) {
        int s0 = __ldg(g_csr + idx);
        int s1 = __ldg(g_csr + idx + 1);
        float a0 = __ldg(g_asrc + (size_t)s0 * HH + head);
        float a1 = __ldg(g_asrc + (size_t)s1 * HH + head);
        float4 h0 = ((const float4*)(g_h + (size_t)s0 * DD))[l];
        float4 h1 = ((const float4*)(g_h + (size_t)s1 * DD))[l];
        float w0 = __expf(lrelu(a0 + adh));
        float w1 = __expf(lrelu(a1 + adh));
        acc.x = fmaf(w0, h0.x, acc.x); acc.y = fmaf(w0, h0.y, acc.y);
        acc.z = fmaf(w0, h0.z, acc.z); acc.w = fmaf(w0, h0.w, acc.w);
        acc.x = fmaf(w1, h1.x, acc.x); acc.y = fmaf(w1, h1.y, acc.y);
        acc.z = fmaf(w1, h1.z, acc.z); acc.w = fmaf(w1, h1.w, acc.w);
        dacc += w0 + w1;
    }
    if (idx < end) {
        int s0 = __ldg(g_csr + idx);
        float a0 = __ldg(g_asrc + (size_t)s0 * HH + head);
        float4 h0 = ((const float4*)(g_h + (size_t)s0 * DD))[l];
        float w0 = __expf(lrelu(a0 + adh));
        acc.x = fmaf(w0, h0.x, acc.x); acc.y = fmaf(w0, h0.y, acc.y);
        acc.z = fmaf(w0, h0.z, acc.z); acc.w = fmaf(w0, h0.w, acc.w);
        dacc += w0;
    }
    float inv = 1.f / dacc;   // denom >= exp(self) > 0 always

    float4 b = ((const float4*)bias)[l];
    float v0 = acc.x * inv + b.x;
    float v1 = acc.y * inv + b.y;
    float v2 = acc.z * inv + b.z;
    float v3 = acc.w * inv + b.w;
    const float kc = 0.70710678118654752f;
    float g0 = 0.5f * v0 * (1.f + erff(v0 * kc));
    float g1 = 0.5f * v1 * (1.f + erff(v1 * kc));
    float g2 = 0.5f * v2 * (1.f + erff(v2 * kc));
    float g3 = 0.5f * v3 * (1.f + erff(v3 * kc));
    float s1 = g0 + g1 + g2 + g3;
    float s2 = g0 * g0 + g1 * g1 + g2 * g2 + g3 * g3;
    #pragma unroll
    for (int o = 16; o; o >>= 1) {
        s1 += __shfl_xor_sync(0xFFFFFFFFu, s1, o);
        s2 += __shfl_xor_sync(0xFFFFFFFFu, s2, o);
    }
    float mean = s1 * (1.f / DD);
    float var  = s2 * (1.f / DD) - mean * mean;
    float invs = rsqrtf(var + 1e-5f);
    float4 ga = ((const float4*)gamma)[l];
    float4 be = ((const float4*)beta)[l];
    float4 xr = ((const float4*)(x + (size_t)n * DD))[l];
    float4 o4;
    o4.x = (g0 - mean) * invs * ga.x + be.x + xr.x;
    o4.y = (g1 - mean) * invs * ga.y + be.y + xr.y;
    o4.z = (g2 - mean) * invs * ga.z + be.z + xr.z;
    o4.w = (g3 - mean) * invs * ga.w + be.w + xr.w;
    ((float4*)(out + (size_t)n * DD))[l] = o4;
}

// ---------------- host -----------------------------------------------------
extern "C" void kernel_launch(void* const* d_in, const int* in_sizes, int n_in,
                              void* d_out, int out_size) {
    const float* x       = (const float*)d_in[0];
    const void*  ei      = d_in[1];  // int32 or int64; sniffed on device
    const float* W       = (const float*)d_in[2];
    const float* att_src = (const float*)d_in[3];
    const float* att_dst = (const float*)d_in[4];
    const float* bias    = (const float*)d_in[5];
    const float* gamma   = (const float*)d_in[6];
    const float* beta    = (const float*)d_in[7];
    float* out = (float*)d_out;

    const int SMEM = (DD * DD + 32 * DD) * (int)sizeof(float);  // 80KB
    cudaFuncSetAttribute(k_gemm, cudaFuncAttributeMaxDynamicSharedMemorySize, SMEM);

    k_init<<<(NN + 255) / 256, 256>>>((const int*)ei);
    k_gemm<<<(NN + 31) / 32, 256, SMEM>>>(x, W, att_src, att_dst);
    k_prep<<<PREP_BLOCKS, 256>>>(ei);
    k_scanA<<<NBLK_SCAN, 256>>>();
    k_scanB<<<1, 256>>>();
    k_scanC<<<NBLK_SCAN, 256>>>();
    k_fill<<<FILL_BLOCKS, 256>>>();
    {
        long long total = (long long)NN * 32;
        int blocks = (int)((total + 255) / 256);
        k_node<<<blocks, 256>>>(x, bias, gamma, beta, out);
    }
}

// round 11
// speedup vs baseline: 2.1569x; 1.0456x over previous
#include <cuda_runtime.h>
#include <math.h>

#define NN 50000
#define EE 600000
#define DD 128
#define HH 4
#define CC 32
#define ETOT (EE + NN)
#define NEG 0.2f
#define NBLK_SCAN ((NN + 255) / 256)   // 196

#define PREP_EPT 4
#define PREP_BLOCKS ((ETOT + 256 * PREP_EPT - 1) / (256 * PREP_EPT))
#define FILL_EPT 4
#define FILL_BLOCKS ((ETOT + 256 * FILL_EPT - 1) / (256 * FILL_EPT))

// ---------------- scratch (device globals; no allocation allowed) ----------
__device__ __align__(16) float g_h[NN * DD];       // transformed feats
__device__ __align__(16) float g_asrc[NN * HH];    // per-node src logits
__device__ __align__(16) float g_adst[NN * HH];    // per-node dst logits
__device__ int g_cnt[NN];                           // degree histogram
__device__ int g_rowtmp[NN];                        // per-chunk exclusive scan
__device__ int g_bsum[NBLK_SCAN];                   // chunk sums
__device__ int g_row[NN + 1];                       // CSR row offsets (by dst)
__device__ int g_csr[ETOT];                         // src per CSR slot
__device__ int g_pos[ETOT];                         // within-row slot per edge
__device__ int g_srcv[ETOT];                        // int32 src per edge
__device__ int g_dstv[ETOT];                        // int32 dst per edge
__device__ int g_is64;                              // edge dtype flag

__device__ __forceinline__ float lrelu(float x) { return x > 0.f ? x : NEG * x; }

__device__ __forceinline__ long long ld_idx(const void* ei, int pos) {
    if (g_is64) return ((const long long*)ei)[pos];
    return (long long)((const int*)ei)[pos];
}

// f32x2 packed-FMA helpers (FFMA2 is only reachable via PTX on sm_103a)
__device__ __forceinline__ unsigned long long pk2(float a, float b) {
    unsigned long long r;
    asm("mov.b64 %0,{%1,%2};" : "=l"(r) : "f"(a), "f"(b));
    return r;
}
__device__ __forceinline__ void upk2(unsigned long long v, float& a, float& b) {
    asm("mov.b64 {%0,%1},%2;" : "=f"(a), "=f"(b) : "l"(v));
}
__device__ __forceinline__ void fma2(unsigned long long& d,
                                     unsigned long long a, unsigned long long b) {
    asm("fma.rn.f32x2 %0,%1,%2,%0;" : "+l"(d) : "l"(a), "l"(b));
}

// ---------------- K0: zero g_cnt + parallel dtype detect -------------------
__global__ void k_init(const int* ei) {
    int i = blockIdx.x * blockDim.x + threadIdx.x;
    if (i < NN) g_cnt[i] = 0;
    if (blockIdx.x == 0 && threadIdx.x < 32) {
        // int64 indices < 2^31: every odd 32-bit word is 0. One word per lane.
        int v = ei[2 * threadIdx.x + 1];
        unsigned nz = __ballot_sync(0xFFFFFFFFu, v != 0);
        if (threadIdx.x == 0) g_is64 = (nz == 0u);
    }
}

// ---------------- K1: h = x @ W (f32x2) + fused attention logits -----------
__global__ void k_gemm(const float* __restrict__ x, const float* __restrict__ W,
                       const float* __restrict__ att_src,
                       const float* __restrict__ att_dst) {
    extern __shared__ float sm[];
    float* Wsh = sm;             // 128*128
    float* Xsh = sm + DD * DD;   // 32*128
    const int tx = threadIdx.x;
    const int node0 = blockIdx.x * 32;

    for (int idx = tx; idx < (DD * DD) / 4; idx += blockDim.x)
        ((float4*)Wsh)[idx] = ((const float4*)W)[idx];

    for (int idx = tx; idx < (32 * DD) / 4; idx += blockDim.x) {
        int r = idx / (DD / 4);
        int c = idx % (DD / 4);
        int row = node0 + r;
        float4 v = make_float4(0.f, 0.f, 0.f, 0.f);
        if (row < NN) v = ((const float4*)(x + (size_t)row * DD))[c];
        ((float4*)(Xsh + r * DD))[c] = v;
    }
    __syncthreads();

    const int c4 = tx & 31;        // 4-col group (cols c4*4 .. c4*4+3)
    const int rb = (tx >> 5) * 4;  // 4-row base within tile
    const float4* Wsh4 = (const float4*)Wsh;
    const float4* Xsh4 = (const float4*)Xsh;

    unsigned long long a01[4], a23[4];
    #pragma unroll
    for (int j = 0; j < 4; j++) { a01[j] = 0ull; a23[j] = 0ull; }

    for (int k4 = 0; k4 < DD / 4; k4++) {
        float xv[4][4];
        #pragma unroll
        for (int j = 0; j < 4; j++) {
            float4 t = Xsh4[(rb + j) * 32 + k4];
            xv[j][0] = t.x; xv[j][1] = t.y; xv[j][2] = t.z; xv[j][3] = t.w;
        }
        #pragma unroll
        for (int kk = 0; kk < 4; kk++) {
            float4 w = Wsh4[(4 * k4 + kk) * 32 + c4];
            unsigned long long wl = pk2(w.x, w.y);
            unsigned long long wh = pk2(w.z, w.w);
            #pragma unroll
            for (int j = 0; j < 4; j++) {
                unsigned long long xx = pk2(xv[j][kk], xv[j][kk]);
                fma2(a01[j], xx, wl);
                fma2(a23[j], xx, wh);
            }
        }
    }

    float accf[4][4];
    #pragma unroll
    for (int j = 0; j < 4; j++) {
        upk2(a01[j], accf[j][0], accf[j][1]);
        upk2(a23[j], accf[j][2], accf[j][3]);
    }

    #pragma unroll
    for (int j = 0; j < 4; j++) {
        int row = node0 + rb + j;
        if (row < NN) {
            float4 o = make_float4(accf[j][0], accf[j][1], accf[j][2], accf[j][3]);
            ((float4*)(g_h + (size_t)row * DD))[c4] = o;
        }
    }

    float4 as4 = ((const float4*)att_src)[c4];
    float4 ad4 = ((const float4*)att_dst)[c4];
    const int head = c4 >> 3;
    #pragma unroll
    for (int j = 0; j < 4; j++) {
        float ps = accf[j][0] * as4.x + accf[j][1] * as4.y +
                   accf[j][2] * as4.z + accf[j][3] * as4.w;
        float pd = accf[j][0] * ad4.x + accf[j][1] * ad4.y +
                   accf[j][2] * ad4.z + accf[j][3] * ad4.w;
        #pragma unroll
        for (int o = 4; o; o >>= 1) {
            ps += __shfl_xor_sync(0xFFFFFFFFu, ps, o);
            pd += __shfl_xor_sync(0xFFFFFFFFu, pd, o);
        }
        int row = node0 + rb + j;
        if ((c4 & 7) == 0 && row < NN) {
            g_asrc[row * HH + head] = ps;
            g_adst[row * HH + head] = pd;
        }
    }
}

// ---------------- K2: edge prep — int32 convert + degree hist + slot -------
__global__ void k_prep(const void* __restrict__ ei) {
    int base = blockIdx.x * 256 * PREP_EPT;
    int s[PREP_EPT], d[PREP_EPT], e[PREP_EPT];
    #pragma unroll
    for (int k = 0; k < PREP_EPT; k++) {
        e[k] = base + k * 256 + threadIdx.x;
        if (e[k] < ETOT) {
            if (e[k] < EE) {
                s[k] = (int)ld_idx(ei, e[k]);
                d[k] = (int)ld_idx(ei, EE + e[k]);
            } else {
                s[k] = d[k] = e[k] - EE;
            }
        }
    }
    #pragma unroll
    for (int k = 0; k < PREP_EPT; k++) {
        if (e[k] < ETOT) {
            g_srcv[e[k]] = s[k];
            g_dstv[e[k]] = d[k];
            g_pos[e[k]] = atomicAdd(&g_cnt[d[k]], 1);
        }
    }
}

// ---------------- K3a/b/c: multi-block exclusive scan g_cnt -> g_row -------
__global__ void k_scanA() {
    __shared__ int wsum[8];
    int i = blockIdx.x * 256 + threadIdx.x;
    int lane = threadIdx.x & 31, w = threadIdx.x >> 5;
    int v = (i < NN) ? g_cnt[i] : 0;
    int xv = v;
    #pragma unroll
    for (int o = 1; o < 32; o <<= 1) {
        int t = __shfl_up_sync(0xFFFFFFFFu, xv, o);
        if (lane >= o) xv += t;
    }
    if (lane == 31) wsum[w] = xv;
    __syncthreads();
    if (w == 0) {
        int s = (lane < 8) ? wsum[lane] : 0;
        #pragma unroll
        for (int o = 1; o < 8; o <<= 1) {
            int t = __shfl_up_sync(0xFFFFFFFFu, s, o);
            if (lane >= o) s += t;
        }
        if (lane < 8) wsum[lane] = s;
    }
    __syncthreads();
    int incl = xv + (w > 0 ? wsum[w - 1] : 0);
    if (i < NN) g_rowtmp[i] = incl - v;
    if (threadIdx.x == 255) g_bsum[blockIdx.x] = incl;
}

__global__ void k_scanB() {
    __shared__ int wsum[8];
    int i = threadIdx.x;
    int lane = i & 31, w = i >> 5;
    int v = (i < NBLK_SCAN) ? g_bsum[i] : 0;
    int xv = v;
    #pragma unroll
    for (int o = 1; o < 32; o <<= 1) {
        int t = __shfl_up_sync(0xFFFFFFFFu, xv, o);
        if (lane >= o) xv += t;
    }
    if (lane == 31) wsum[w] = xv;
    __syncthreads();
    if (w == 0) {
        int s = (lane < 8) ? wsum[lane] : 0;
        #pragma unroll
        for (int o = 1; o < 8; o <<= 1) {
            int t = __shfl_up_sync(0xFFFFFFFFu, s, o);
            if (lane >= o) s += t;
        }
        if (lane < 8) wsum[lane] = s;
    }
    __syncthreads();
    int incl = xv + (w > 0 ? wsum[w - 1] : 0);
    if (i < NBLK_SCAN) g_bsum[i] = incl - v;  // exclusive
}

__global__ void k_scanC() {
    int i = blockIdx.x * 256 + threadIdx.x;
    if (i < NN) g_row[i] = g_rowtmp[i] + g_bsum[blockIdx.x];
    if (i == 0) g_row[NN] = ETOT;
}

// ---------------- K4: fill CSR (no atomics — slot precomputed) -------------
__global__ void k_fill() {
    int base = blockIdx.x * 256 * FILL_EPT;
    #pragma unroll
    for (int k = 0; k < FILL_EPT; k++) {
        int e = base + k * 256 + threadIdx.x;
        if (e < ETOT)
            g_csr[g_row[g_dstv[e]] + g_pos[e]] = g_srcv[e];
    }
}

// ---------------- K5: fused softmax + aggregation + GELU/LN/residual -------
__global__ void k_node(const float* __restrict__ x,
                       const float* __restrict__ bias,
                       const float* __restrict__ gamma,
                       const float* __restrict__ beta,
                       float* __restrict__ out) {
    int gid = blockIdx.x * blockDim.x + threadIdx.x;
    int n = gid >> 5;
    if (n >= NN) return;
    int l = gid & 31;
    int head = l >> 3;
    int beg = g_row[n], end = g_row[n + 1];
    float adh = g_adst[(size_t)n * HH + head];

    float4 acc = make_float4(0.f, 0.f, 0.f, 0.f);
    float dacc = 0.f;
    int idx = beg;
    for (; idx + 1 < end; idx += 2) {
        int s0 = __ldg(g_csr + idx);
        int s1 = __ldg(g_csr + idx + 1);
        float a0 = __ldg(g_asrc + (size_t)s0 * HH + head);
        float a1 = __ldg(g_asrc + (size_t)s1 * HH + head);
        float4 h0 = ((const float4*)(g_h + (size_t)s0 * DD))[l];
        float4 h1 = ((const float4*)(g_h + (size_t)s1 * DD))[l];
        float w0 = __expf(lrelu(a0 + adh));
        float w1 = __expf(lrelu(a1 + adh));
        acc.x = fmaf(w0, h0.x, acc.x); acc.y = fmaf(w0, h0.y, acc.y);
        acc.z = fmaf(w0, h0.z, acc.z); acc.w = fmaf(w0, h0.w, acc.w);
        acc.x = fmaf(w1, h1.x, acc.x); acc.y = fmaf(w1, h1.y, acc.y);
        acc.z = fmaf(w1, h1.z, acc.z); acc.w = fmaf(w1, h1.w, acc.w);
        dacc += w0 + w1;
    }
    if (idx < end) {
        int s0 = __ldg(g_csr + idx);
        float a0 = __ldg(g_asrc + (size_t)s0 * HH + head);
        float4 h0 = ((const float4*)(g_h + (size_t)s0 * DD))[l];
        float w0 = __expf(lrelu(a0 + adh));
        acc.x = fmaf(w0, h0.x, acc.x); acc.y = fmaf(w0, h0.y, acc.y);
        acc.z = fmaf(w0, h0.z, acc.z); acc.w = fmaf(w0, h0.w, acc.w);
        dacc += w0;
    }
    float inv = 1.f / dacc;   // denom >= exp(self) > 0 always

    float4 b = ((const float4*)bias)[l];
    float v0 = acc.x * inv + b.x;
    float v1 = acc.y * inv + b.y;
    float v2 = acc.z * inv + b.z;
    float v3 = acc.w * inv + b.w;
    const float kc = 0.70710678118654752f;
    float g0 = 0.5f * v0 * (1.f + erff(v0 * kc));
    float g1 = 0.5f * v1 * (1.f + erff(v1 * kc));
    float g2 = 0.5f * v2 * (1.f + erff(v2 * kc));
    float g3 = 0.5f * v3 * (1.f + erff(v3 * kc));
    float s1 = g0 + g1 + g2 + g3;
    float s2 = g0 * g0 + g1 * g1 + g2 * g2 + g3 * g3;
    #pragma unroll
    for (int o = 16; o; o >>= 1) {
        s1 += __shfl_xor_sync(0xFFFFFFFFu, s1, o);
        s2 += __shfl_xor_sync(0xFFFFFFFFu, s2, o);
    }
    float mean = s1 * (1.f / DD);
    float var  = s2 * (1.f / DD) - mean * mean;
    float invs = rsqrtf(var + 1e-5f);
    float4 ga = ((const float4*)gamma)[l];
    float4 be = ((const float4*)beta)[l];
    float4 xr = ((const float4*)(x + (size_t)n * DD))[l];
    float4 o4;
    o4.x = (g0 - mean) * invs * ga.x + be.x + xr.x;
    o4.y = (g1 - mean) * invs * ga.y + be.y + xr.y;
    o4.z = (g2 - mean) * invs * ga.z + be.z + xr.z;
    o4.w = (g3 - mean) * invs * ga.w + be.w + xr.w;
    ((float4*)(out + (size_t)n * DD))[l] = o4;
}

// ---------------- host -----------------------------------------------------
extern "C" void kernel_launch(void* const* d_in, const int* in_sizes, int n_in,
                              void* d_out, int out_size) {
    const float* x       = (const float*)d_in[0];
    const void*  ei      = d_in[1];  // int32 or int64; sniffed on device
    const float* W       = (const float*)d_in[2];
    const float* att_src = (const float*)d_in[3];
    const float* att_dst = (const float*)d_in[4];
    const float* bias    = (const float*)d_in[5];
    const float* gamma   = (const float*)d_in[6];
    const float* beta    = (const float*)d_in[7];
    float* out = (float*)d_out;

    const int SMEM = (DD * DD + 32 * DD) * (int)sizeof(float);  // 80KB
    cudaFuncSetAttribute(k_gemm, cudaFuncAttributeMaxDynamicSharedMemorySize, SMEM);

    // Fork a side stream so the CSR build (edge-index only) overlaps the GEMM
    // (x/W only). Standard capture-safe fork/join via events; they join before
    // k_node, which needs both.
    cudaStream_t side;
    cudaEvent_t evRoot, evSide;
    cudaStreamCreateWithFlags(&side, cudaStreamNonBlocking);
    cudaEventCreateWithFlags(&evRoot, cudaEventDisableTiming);
    cudaEventCreateWithFlags(&evSide, cudaEventDisableTiming);

    cudaEventRecord(evRoot, 0);
    cudaStreamWaitEvent(side, evRoot, 0);

    // side: CSR build chain
    k_init<<<(NN + 255) / 256, 256, 0, side>>>((const int*)ei);
    k_prep<<<PREP_BLOCKS, 256, 0, side>>>(ei);
    k_scanA<<<NBLK_SCAN, 256, 0, side>>>();
    k_scanB<<<1, 256, 0, side>>>();
    k_scanC<<<NBLK_SCAN, 256, 0, side>>>();
    k_fill<<<FILL_BLOCKS, 256, 0, side>>>();
    cudaEventRecord(evSide, side);

    // main: GEMM runs concurrently with the side chain
    k_gemm<<<(NN + 31) / 32, 256, SMEM>>>(x, W, att_src, att_dst);

    // join, then the fused node kernel (needs h/logits AND the CSR)
    cudaStreamWaitEvent(0, evSide, 0);
    {
        long long total = (long long)NN * 32;
        int blocks = (int)((total + 255) / 256);
        k_node<<<blocks, 256>>>(x, bias, gamma, beta, out);
    }

    cudaEventDestroy(evRoot);
    cudaEventDestroy(evSide);
    cudaStreamDestroy(side);
}

// round 14
// speedup vs baseline: 2.2766x; 1.0555x over previous
#include <cuda_runtime.h>
#include <cuda_fp16.h>
#include <math.h>

#define NN 50000
#define EE 600000
#define DD 128
#define HH 4
#define CC 32
#define ETOT (EE + NN)
#define NEG 0.2f
#define NBLK_SCAN ((NN + 255) / 256)   // 196

#define PREP_EPT 4
#define PREP_BLOCKS ((ETOT + 256 * PREP_EPT - 1) / (256 * PREP_EPT))
#define FILL_EPT 4
#define FILL_BLOCKS ((ETOT + 256 * FILL_EPT - 1) / (256 * FILL_EPT))

// ---------------- scratch (device globals; no allocation allowed) ----------
__device__ __align__(16) __half g_hh[NN * DD];     // transformed feats (fp16)
__device__ __align__(16) float g_asrc[NN * HH];    // per-node src logits (fp32)
__device__ __align__(16) float g_adst[NN * HH];    // per-node dst logits (fp32)
__device__ int g_cnt[NN];                           // degree histogram
__device__ int g_rowtmp[NN];                        // per-chunk exclusive scan
__device__ int g_bsum[NBLK_SCAN];                   // chunk sums
__device__ int g_row[NN + 1];                       // CSR row offsets (by dst)
__device__ int g_csr[ETOT];                         // src per CSR slot
__device__ int g_pos[ETOT];                         // within-row slot per edge
__device__ int g_srcv[ETOT];                        // int32 src per edge
__device__ int g_dstv[ETOT];                        // int32 dst per edge
__device__ int g_is64;                              // edge dtype flag

struct __align__(8) h4pack { __half2 a, b; };       // 4 halfs = 8 bytes

__device__ __forceinline__ float lrelu(float x) { return x > 0.f ? x : NEG * x; }

__device__ __forceinline__ long long ld_idx(const void* ei, int pos) {
    if (g_is64) return ((const long long*)ei)[pos];
    return (long long)((const int*)ei)[pos];
}

// f32x2 packed-FMA helpers (FFMA2 is only reachable via PTX on sm_103a)
__device__ __forceinline__ unsigned long long pk2(float a, float b) {
    unsigned long long r;
    asm("mov.b64 %0,{%1,%2};" : "=l"(r) : "f"(a), "f"(b));
    return r;
}
__device__ __forceinline__ void upk2(unsigned long long v, float& a, float& b) {
    asm("mov.b64 {%0,%1},%2;" : "=f"(a), "=f"(b) : "l"(v));
}
__device__ __forceinline__ void fma2(unsigned long long& d,
                                     unsigned long long a, unsigned long long b) {
    asm("fma.rn.f32x2 %0,%1,%2,%0;" : "+l"(d) : "l"(a), "l"(b));
}

// ---------------- K0: zero g_cnt + parallel dtype detect -------------------
__global__ void k_init(const int* ei) {
    int i = blockIdx.x * blockDim.x + threadIdx.x;
    if (i < NN) g_cnt[i] = 0;
    if (blockIdx.x == 0 && threadIdx.x < 32) {
        // int64 indices < 2^31: every odd 32-bit word is 0. One word per lane.
        int v = ei[2 * threadIdx.x + 1];
        unsigned nz = __ballot_sync(0xFFFFFFFFu, v != 0);
        if (threadIdx.x == 0) g_is64 = (nz == 0u);
    }
}

// ---------------- K1: h = x @ W (f32x2) + fused logits; h stored fp16 ------
__global__ void k_gemm(const float* __restrict__ x, const float* __restrict__ W,
                       const float* __restrict__ att_src,
                       const float* __restrict__ att_dst) {
    extern __shared__ float sm[];
    float* Wsh = sm;             // 128*128
    float* Xsh = sm + DD * DD;   // 32*128
    const int tx = threadIdx.x;
    const int node0 = blockIdx.x * 32;

    for (int idx = tx; idx < (DD * DD) / 4; idx += blockDim.x)
        ((float4*)Wsh)[idx] = ((const float4*)W)[idx];

    for (int idx = tx; idx < (32 * DD) / 4; idx += blockDim.x) {
        int r = idx / (DD / 4);
        int c = idx % (DD / 4);
        int row = node0 + r;
        float4 v = make_float4(0.f, 0.f, 0.f, 0.f);
        if (row < NN) v = ((const float4*)(x + (size_t)row * DD))[c];
        ((float4*)(Xsh + r * DD))[c] = v;
    }
    __syncthreads();

    const int c4 = tx & 31;        // 4-col group (cols c4*4 .. c4*4+3)
    const int rb = (tx >> 5) * 4;  // 4-row base within tile
    const float4* Wsh4 = (const float4*)Wsh;
    const float4* Xsh4 = (const float4*)Xsh;

    unsigned long long a01[4], a23[4];
    #pragma unroll
    for (int j = 0; j < 4; j++) { a01[j] = 0ull; a23[j] = 0ull; }

    for (int k4 = 0; k4 < DD / 4; k4++) {
        float xv[4][4];
        #pragma unroll
        for (int j = 0; j < 4; j++) {
            float4 t = Xsh4[(rb + j) * 32 + k4];
            xv[j][0] = t.x; xv[j][1] = t.y; xv[j][2] = t.z; xv[j][3] = t.w;
        }
        #pragma unroll
        for (int kk = 0; kk < 4; kk++) {
            float4 w = Wsh4[(4 * k4 + kk) * 32 + c4];
            unsigned long long wl = pk2(w.x, w.y);
            unsigned long long wh = pk2(w.z, w.w);
            #pragma unroll
            for (int j = 0; j < 4; j++) {
                unsigned long long xx = pk2(xv[j][kk], xv[j][kk]);
                fma2(a01[j], xx, wl);
                fma2(a23[j], xx, wh);
            }
        }
    }

    float accf[4][4];
    #pragma unroll
    for (int j = 0; j < 4; j++) {
        upk2(a01[j], accf[j][0], accf[j][1]);
        upk2(a23[j], accf[j][2], accf[j][3]);
    }

    // store h as fp16 (4 halfs = 8B per lane)
    #pragma unroll
    for (int j = 0; j < 4; j++) {
        int row = node0 + rb + j;
        if (row < NN) {
            h4pack p;
            p.a = __floats2half2_rn(accf[j][0], accf[j][1]);
            p.b = __floats2half2_rn(accf[j][2], accf[j][3]);
            ((h4pack*)(g_hh + (size_t)row * DD))[c4] = p;
        }
    }

    // logits from the EXACT fp32 accumulators (softmax weights unperturbed)
    float4 as4 = ((const float4*)att_src)[c4];
    float4 ad4 = ((const float4*)att_dst)[c4];
    const int head = c4 >> 3;
    #pragma unroll
    for (int j = 0; j < 4; j++) {
        float ps = accf[j][0] * as4.x + accf[j][1] * as4.y +
                   accf[j][2] * as4.z + accf[j][3] * as4.w;
        float pd = accf[j][0] * ad4.x + accf[j][1] * ad4.y +
                   accf[j][2] * ad4.z + accf[j][3] * ad4.w;
        #pragma unroll
        for (int o = 4; o; o >>= 1) {
            ps += __shfl_xor_sync(0xFFFFFFFFu, ps, o);
            pd += __shfl_xor_sync(0xFFFFFFFFu, pd, o);
        }
        int row = node0 + rb + j;
        if ((c4 & 7) == 0 && row < NN) {
            g_asrc[row * HH + head] = ps;
            g_adst[row * HH + head] = pd;
        }
    }
}

// ---------------- K2: edge prep — int32 convert + degree hist + slot -------
__global__ void k_prep(const void* __restrict__ ei) {
    int base = blockIdx.x * 256 * PREP_EPT;
    int s[PREP_EPT], d[PREP_EPT], e[PREP_EPT];
    #pragma unroll
    for (int k = 0; k < PREP_EPT; k++) {
        e[k] = base + k * 256 + threadIdx.x;
        if (e[k] < ETOT) {
            if (e[k] < EE) {
                s[k] = (int)ld_idx(ei, e[k]);
                d[k] = (int)ld_idx(ei, EE + e[k]);
            } else {
                s[k] = d[k] = e[k] - EE;
            }
        }
    }
    #pragma unroll
    for (int k = 0; k < PREP_EPT; k++) {
        if (e[k] < ETOT) {
            g_srcv[e[k]] = s[k];
            g_dstv[e[k]] = d[k];
            g_pos[e[k]] = atomicAdd(&g_cnt[d[k]], 1);
        }
    }
}

// ---------------- K3a/b/c: multi-block exclusive scan g_cnt -> g_row -------
__global__ void k_scanA() {
    __shared__ int wsum[8];
    int i = blockIdx.x * 256 + threadIdx.x;
    int lane = threadIdx.x & 31, w = threadIdx.x >> 5;
    int v = (i < NN) ? g_cnt[i] : 0;
    int xv = v;
    #pragma unroll
    for (int o = 1; o < 32; o <<= 1) {
        int t = __shfl_up_sync(0xFFFFFFFFu, xv, o);
        if (lane >= o) xv += t;
    }
    if (lane == 31) wsum[w] = xv;
    __syncthreads();
    if (w == 0) {
        int s = (lane < 8) ? wsum[lane] : 0;
        #pragma unroll
        for (int o = 1; o < 8; o <<= 1) {
            int t = __shfl_up_sync(0xFFFFFFFFu, s, o);
            if (lane >= o) s += t;
        }
        if (lane < 8) wsum[lane] = s;
    }
    __syncthreads();
    int incl = xv + (w > 0 ? wsum[w - 1] : 0);
    if (i < NN) g_rowtmp[i] = incl - v;
    if (threadIdx.x == 255) g_bsum[blockIdx.x] = incl;
}

__global__ void k_scanB() {
    __shared__ int wsum[8];
    int i = threadIdx.x;
    int lane = i & 31, w = i >> 5;
    int v = (i < NBLK_SCAN) ? g_bsum[i] : 0;
    int xv = v;
    #pragma unroll
    for (int o = 1; o < 32; o <<= 1) {
        int t = __shfl_up_sync(0xFFFFFFFFu, xv, o);
        if (lane >= o) xv += t;
    }
    if (lane == 31) wsum[w] = xv;
    __syncthreads();
    if (w == 0) {
        int s = (lane < 8) ? wsum[lane] : 0;
        #pragma unroll
        for (int o = 1; o < 8; o <<= 1) {
            int t = __shfl_up_sync(0xFFFFFFFFu, s, o);
            if (lane >= o) s += t;
        }
        if (lane < 8) wsum[lane] = s;
    }
    __syncthreads();
    int incl = xv + (w > 0 ? wsum[w - 1] : 0);
    if (i < NBLK_SCAN) g_bsum[i] = incl - v;  // exclusive
}

__global__ void k_scanC() {
    int i = blockIdx.x * 256 + threadIdx.x;
    if (i < NN) g_row[i] = g_rowtmp[i] + g_bsum[blockIdx.x];
    if (i == 0) g_row[NN] = ETOT;
}

// ---------------- K4: fill CSR (no atomics — slot precomputed) -------------
__global__ void k_fill() {
    int base = blockIdx.x * 256 * FILL_EPT;
    #pragma unroll
    for (int k = 0; k < FILL_EPT; k++) {
        int e = base + k * 256 + threadIdx.x;
        if (e < ETOT)
            g_csr[g_row[g_dstv[e]] + g_pos[e]] = g_srcv[e];
    }
}

// ---------------- K5: fused softmax + aggregation + GELU/LN/residual -------
__global__ void k_node(const float* __restrict__ x,
                       const float* __restrict__ bias,
                       const float* __restrict__ gamma,
                       const float* __restrict__ beta,
                       float* __restrict__ out) {
    int gid = blockIdx.x * blockDim.x + threadIdx.x;
    int n = gid >> 5;
    if (n >= NN) return;
    int l = gid & 31;
    int head = l >> 3;
    int beg = g_row[n], end = g_row[n + 1];
    float adh = g_adst[(size_t)n * HH + head];

    float4 acc = make_float4(0.f, 0.f, 0.f, 0.f);
    float dacc = 0.f;
    int idx = beg;
    for (; idx + 1 < end; idx += 2) {
        int s0 = __ldg(g_csr + idx);
        int s1 = __ldg(g_csr + idx + 1);
        float a0 = __ldg(g_asrc + (size_t)s0 * HH + head);
        float a1 = __ldg(g_asrc + (size_t)s1 * HH + head);
        h4pack p0 = ((const h4pack*)(g_hh + (size_t)s0 * DD))[l];
        h4pack p1 = ((const h4pack*)(g_hh + (size_t)s1 * DD))[l];
        float w0 = __expf(lrelu(a0 + adh));
        float w1 = __expf(lrelu(a1 + adh));
        float2 f0a = __half22float2(p0.a), f0b = __half22float2(p0.b);
        float2 f1a = __half22float2(p1.a), f1b = __half22float2(p1.b);
        acc.x = fmaf(w0, f0a.x, acc.x); acc.y = fmaf(w0, f0a.y, acc.y);
        acc.z = fmaf(w0, f0b.x, acc.z); acc.w = fmaf(w0, f0b.y, acc.w);
        acc.x = fmaf(w1, f1a.x, acc.x); acc.y = fmaf(w1, f1a.y, acc.y);
        acc.z = fmaf(w1, f1b.x, acc.z); acc.w = fmaf(w1, f1b.y, acc.w);
        dacc += w0 + w1;
    }
    if (idx < end) {
        int s0 = __ldg(g_csr + idx);
        float a0 = __ldg(g_asrc + (size_t)s0 * HH + head);
        h4pack p0 = ((const h4pack*)(g_hh + (size_t)s0 * DD))[l];
        float w0 = __expf(lrelu(a0 + adh));
        float2 f0a = __half22float2(p0.a), f0b = __half22float2(p0.b);
        acc.x = fmaf(w0, f0a.x, acc.x); acc.y = fmaf(w0, f0a.y, acc.y);
        acc.z = fmaf(w0, f0b.x, acc.z); acc.w = fmaf(w0, f0b.y, acc.w);
        dacc += w0;
    }
    float inv = 1.f / dacc;   // denom >= exp(self) > 0 always

    float4 b = ((const float4*)bias)[l];
    float v0 = acc.x * inv + b.x;
    float v1 = acc.y * inv + b.y;
    float v2 = acc.z * inv + b.z;
    float v3 = acc.w * inv + b.w;
    const float kc = 0.70710678118654752f;
    float g0 = 0.5f * v0 * (1.f + erff(v0 * kc));
    float g1 = 0.5f * v1 * (1.f + erff(v1 * kc));
    float g2 = 0.5f * v2 * (1.f + erff(v2 * kc));
    float g3 = 0.5f * v3 * (1.f + erff(v3 * kc));
    float s1 = g0 + g1 + g2 + g3;
    float s2 = g0 * g0 + g1 * g1 + g2 * g2 + g3 * g3;
    #pragma unroll
    for (int o = 16; o; o >>= 1) {
        s1 += __shfl_xor_sync(0xFFFFFFFFu, s1, o);
        s2 += __shfl_xor_sync(0xFFFFFFFFu, s2, o);
    }
    float mean = s1 * (1.f / DD);
    float var  = s2 * (1.f / DD) - mean * mean;
    float invs = rsqrtf(var + 1e-5f);
    float4 ga = ((const float4*)gamma)[l];
    float4 be = ((const float4*)beta)[l];
    float4 xr = ((const float4*)(x + (size_t)n * DD))[l];
    float4 o4;
    o4.x = (g0 - mean) * invs * ga.x + be.x + xr.x;
    o4.y = (g1 - mean) * invs * ga.y + be.y + xr.y;
    o4.z = (g2 - mean) * invs * ga.z + be.z + xr.z;
    o4.w = (g3 - mean) * invs * ga.w + be.w + xr.w;
    ((float4*)(out + (size_t)n * DD))[l] = o4;
}

// ---------------- host -----------------------------------------------------
extern "C" void kernel_launch(void* const* d_in, const int* in_sizes, int n_in,
                              void* d_out, int out_size) {
    const float* x       = (const float*)d_in[0];
    const void*  ei      = d_in[1];  // int32 or int64; sniffed on device
    const float* W       = (const float*)d_in[2];
    const float* att_src = (const float*)d_in[3];
    const float* att_dst = (const float*)d_in[4];
    const float* bias    = (const float*)d_in[5];
    const float* gamma   = (const float*)d_in[6];
    const float* beta    = (const float*)d_in[7];
    float* out = (float*)d_out;

    const int SMEM = (DD * DD + 32 * DD) * (int)sizeof(float);  // 80KB
    cudaFuncSetAttribute(k_gemm, cudaFuncAttributeMaxDynamicSharedMemorySize, SMEM);

    // Fork a side stream so the CSR build (edge-index only) overlaps the GEMM
    // (x/W only). Capture-safe fork/join via events; joined before k_node.
    cudaStream_t side;
    cudaEvent_t evRoot, evSide;
    cudaStreamCreateWithFlags(&side, cudaStreamNonBlocking);
    cudaEventCreateWithFlags(&evRoot, cudaEventDisableTiming);
    cudaEventCreateWithFlags(&evSide, cudaEventDisableTiming);

    cudaEventRecord(evRoot, 0);
    cudaStreamWaitEvent(side, evRoot, 0);

    // side: CSR build chain
    k_init<<<(NN + 255) / 256, 256, 0, side>>>((const int*)ei);
    k_prep<<<PREP_BLOCKS, 256, 0, side>>>(ei);
    k_scanA<<<NBLK_SCAN, 256, 0, side>>>();
    k_scanB<<<1, 256, 0, side>>>();
    k_scanC<<<NBLK_SCAN, 256, 0, side>>>();
    k_fill<<<FILL_BLOCKS, 256, 0, side>>>();
    cudaEventRecord(evSide, side);

    // main: GEMM runs concurrently with the side chain
    k_gemm<<<(NN + 31) / 32, 256, SMEM>>>(x, W, att_src, att_dst);

    // join, then the fused node kernel (needs h/logits AND the CSR)
    cudaStreamWaitEvent(0, evSide, 0);
    {
        long long total = (long long)NN * 32;
        int blocks = (int)((total + 255) / 256);
        k_node<<<blocks, 256>>>(x, bias, gamma, beta, out);
    }

    cudaEventDestroy(evRoot);
    cudaEventDestroy(evSide);
    cudaStreamDestroy(side);
}